// round 17
// baseline (speedup 1.0000x reference)
#include <cuda_runtime.h>
#include <cuda_bf16.h>
#include <cstdint>

// Problem constants: B=2, N=2048, E=1024, H=16, D=64
// M = B*N = 4096 flattened rows. QKV fused width = 1024 + 64 + 64 = 1152.

#define CDIV(a, b) (((a) + (b) - 1) / (b))

// ---------------------------------------------------------------------------
// Scratch (__device__ globals; allocation-free rule)
// ---------------------------------------------------------------------------
__device__ __nv_bfloat16   g_QKVhi[4096 * 1152];  // [Q|K|V] hi, Q pre-scaled by 1/8
__device__ __nv_bfloat16   g_QKVlo[4096 * 1152];
__device__ __nv_bfloat16   g_Xhi[4096 * 1024];
__device__ __nv_bfloat16   g_Xlo[4096 * 1024];
__device__ __nv_bfloat16   g_Wthi[1152 * 1024];  // [Wq/8|Wk|Wv]^T (N-major, K contig)
__device__ __nv_bfloat16   g_Wtlo[1152 * 1024];
__device__ __nv_bfloat16   g_Wothi[1024 * 1024]; // Wo^T
__device__ __nv_bfloat16   g_Wotlo[1024 * 1024];
__device__ __nv_bfloat16   g_Zhi[4096 * 1024];   // attention output, split
__device__ __nv_bfloat16   g_Zlo[4096 * 1024];

// ---------------------------------------------------------------------------
// Helpers
// ---------------------------------------------------------------------------
__device__ __forceinline__ uint32_t smem_to_u32(const void* p) {
    uint32_t a;
    asm("{ .reg .u64 t; cvta.to.shared.u64 t, %1; cvt.u32.u64 %0, t; }"
        : "=r"(a) : "l"(p));
    return a;
}

__device__ __forceinline__ void ldmatrix_x4(uint32_t* r, uint32_t addr) {
    asm volatile(
        "ldmatrix.sync.aligned.m8n8.x4.shared.b16 {%0, %1, %2, %3}, [%4];"
        : "=r"(r[0]), "=r"(r[1]), "=r"(r[2]), "=r"(r[3]) : "r"(addr));
}

__device__ __forceinline__ void ldmatrix_x4_trans(uint32_t* r, uint32_t addr) {
    asm volatile(
        "ldmatrix.sync.aligned.m8n8.x4.trans.shared.b16 {%0, %1, %2, %3}, [%4];"
        : "=r"(r[0]), "=r"(r[1]), "=r"(r[2]), "=r"(r[3]) : "r"(addr));
}

__device__ __forceinline__ void mma_bf16(float* d, const uint32_t* a,
                                         uint32_t b0, uint32_t b1) {
    asm volatile(
        "mma.sync.aligned.m16n8k16.row.col.f32.bf16.bf16.f32 "
        "{%0, %1, %2, %3}, {%4, %5, %6, %7}, {%8, %9}, {%0, %1, %2, %3};"
        : "+f"(d[0]), "+f"(d[1]), "+f"(d[2]), "+f"(d[3])
        : "r"(a[0]), "r"(a[1]), "r"(a[2]), "r"(a[3]), "r"(b0), "r"(b1));
}

__device__ __forceinline__ uint32_t pack2(__nv_bfloat16 a, __nv_bfloat16 b) {
    __nv_bfloat162 t = __halves2bfloat162(a, b);
    return *reinterpret_cast<uint32_t*>(&t);
}

__device__ __forceinline__ uint32_t pack_bf16f(float a, float b) {
    return pack2(__float2bfloat16(a), __float2bfloat16(b));
}

// write hi(x),hi(y) to hi and residuals to lo (2 contiguous bf16 each)
__device__ __forceinline__ void split2_store(float x, float y,
                                             __nv_bfloat16* hi, __nv_bfloat16* lo) {
    __nv_bfloat16 hx = __float2bfloat16(x), hy = __float2bfloat16(y);
    *(__nv_bfloat162*)hi = __halves2bfloat162(hx, hy);
    *(__nv_bfloat162*)lo = __halves2bfloat162(
        __float2bfloat16(x - __bfloat162float(hx)),
        __float2bfloat16(y - __bfloat162float(hy)));
}

#define CP_ASYNC16(dst_u32, src_ptr)                                           \
    asm volatile("cp.async.cg.shared.global [%0], [%1], 16;"                   \
                 :: "r"(dst_u32), "l"(src_ptr))
#define CP_COMMIT()  asm volatile("cp.async.commit_group;" ::: "memory")
#define CP_WAIT1()   asm volatile("cp.async.wait_group 1;" ::: "memory")
#define CP_WAIT0()   asm volatile("cp.async.wait_group 0;" ::: "memory")

// ---------------------------------------------------------------------------
// Precision-split conversion: x -> hi = bf16(x), lo = bf16(x - hi)
// ---------------------------------------------------------------------------
__global__ void split_f32_bf16(const float* __restrict__ x,
                               __nv_bfloat16* __restrict__ hi,
                               __nv_bfloat16* __restrict__ lo, int n4) {
    int i = blockIdx.x * 256 + threadIdx.x;
    if (i >= n4) return;
    float4 v = ((const float4*)x)[i];
    __nv_bfloat16 h0 = __float2bfloat16(v.x), h1 = __float2bfloat16(v.y);
    __nv_bfloat16 h2 = __float2bfloat16(v.z), h3 = __float2bfloat16(v.w);
    __nv_bfloat16 l0 = __float2bfloat16(v.x - __bfloat162float(h0));
    __nv_bfloat16 l1 = __float2bfloat16(v.y - __bfloat162float(h1));
    __nv_bfloat16 l2 = __float2bfloat16(v.z - __bfloat162float(h2));
    __nv_bfloat16 l3 = __float2bfloat16(v.w - __bfloat162float(h3));
    ((__nv_bfloat162*)hi)[2 * i + 0] = __halves2bfloat162(h0, h1);
    ((__nv_bfloat162*)hi)[2 * i + 1] = __halves2bfloat162(h2, h3);
    ((__nv_bfloat162*)lo)[2 * i + 0] = __halves2bfloat162(l0, l1);
    ((__nv_bfloat162*)lo)[2 * i + 1] = __halves2bfloat162(l2, l3);
}

// Build W_all^T (1152 x 1024) split into hi/lo. Wq columns pre-scaled by 1/8
// (exact power of two, equivalent to scaling scores by 1/sqrt(D)).
__global__ void build_wall_t(const float* __restrict__ Wq,
                             const float* __restrict__ Wk,
                             const float* __restrict__ Wv,
                             __nv_bfloat16* __restrict__ hi,
                             __nv_bfloat16* __restrict__ lo) {
    int i = blockIdx.x * 256 + threadIdx.x;
    if (i >= 1152 * 1024) return;
    int n = i >> 10;
    int k = i & 1023;
    float v;
    if (n < 1024)      v = Wq[k * 1024 + n] * 0.125f;
    else if (n < 1088) v = Wk[k * 64 + (n - 1024)];
    else               v = Wv[k * 64 + (n - 1088)];
    __nv_bfloat16 h = __float2bfloat16(v);
    hi[i] = h;
    lo[i] = __float2bfloat16(v - __bfloat162float(h));
}

// Wo^T (1024 x 1024) split into hi/lo
__global__ void build_wo_t(const float* __restrict__ Wo,
                           __nv_bfloat16* __restrict__ hi,
                           __nv_bfloat16* __restrict__ lo) {
    int i = blockIdx.x * 256 + threadIdx.x;
    if (i >= 1024 * 1024) return;
    int n = i >> 10;
    int k = i & 1023;
    float v = Wo[k * 1024 + n];
    __nv_bfloat16 h = __float2bfloat16(v);
    hi[i] = h;
    lo[i] = __float2bfloat16(v - __bfloat162float(h));
}

// ---------------------------------------------------------------------------
// HMMA GEMM (mma.sync m16n8k16 bf16, split precision x3), cp.async
// double-buffered, term-major MMA interleave (dependency distance 4).
// ---------------------------------------------------------------------------
#define LDT 40
#define TILE_BYTES  (128 * LDT * 2)      // 10240
#define STAGE_BYTES (4 * TILE_BYTES)     // 40960
#define GEMM_DSMEM  (2 * STAGE_BYTES)    // 81920

template <bool SPLIT_OUT>
__global__ __launch_bounds__(256, 2)
void hmma_gemm(const __nv_bfloat16* __restrict__ Ahi, const __nv_bfloat16* __restrict__ Alo,
               const __nv_bfloat16* __restrict__ Bhi, const __nv_bfloat16* __restrict__ Blo,
               float* __restrict__ C, const float* __restrict__ bias,
               __nv_bfloat16* __restrict__ Chi, __nv_bfloat16* __restrict__ Clo,
               int K, int ldc) {
    extern __shared__ __nv_bfloat16 dsm[];
    const uint32_t smb = smem_to_u32(dsm);

    const int tid  = threadIdx.x;
    const int lane = tid & 31;
    const int wid  = tid >> 5;
    const int warp_row = wid & 3;
    const int warp_col = wid >> 2;
    const int cRow = blockIdx.y * 128;
    const int cCol = blockIdx.x * 128;

    const int lrow = tid >> 1;
    const int seg  = (tid & 1) * 16;
    const __nv_bfloat16* gsrc[4];
    gsrc[0] = Ahi + (size_t)(cRow + lrow) * K + seg;
    gsrc[1] = Alo + (size_t)(cRow + lrow) * K + seg;
    gsrc[2] = Bhi + (size_t)(cCol + lrow) * K + seg;
    gsrc[3] = Blo + (size_t)(cCol + lrow) * K + seg;
    const uint32_t st_off = (uint32_t)(lrow * LDT + seg) * 2;

    const uint32_t aoff =
        ((uint32_t)(warp_row * 32 + (lane & 15)) * LDT + ((lane >> 4) << 3)) * 2;
    const uint32_t boff =
        ((uint32_t)(warp_col * 64 + (lane & 7) + ((lane >> 4) << 3)) * LDT +
         (((lane >> 3) & 1) << 3)) * 2;

    float acc[2][8][4];
#pragma unroll
    for (int mi = 0; mi < 2; mi++)
#pragma unroll
        for (int ni = 0; ni < 8; ni++)
#pragma unroll
            for (int j = 0; j < 4; j++) acc[mi][ni][j] = 0.0f;

    const int nch = K >> 5;

    // prologue: stream chunk 0 into stage 0
#pragma unroll
    for (int t = 0; t < 4; t++) {
        const uint32_t d = smb + t * TILE_BYTES + st_off;
        CP_ASYNC16(d,      gsrc[t]);
        CP_ASYNC16(d + 16, gsrc[t] + 8);
    }
    CP_COMMIT();

    for (int ch = 0; ch < nch; ch++) {
        if (ch + 1 < nch) {
            const uint32_t sb = smb + ((ch + 1) & 1) * STAGE_BYTES;
            const int k0 = (ch + 1) * 32;
#pragma unroll
            for (int t = 0; t < 4; t++) {
                const uint32_t d = sb + t * TILE_BYTES + st_off;
                CP_ASYNC16(d,      gsrc[t] + k0);
                CP_ASYNC16(d + 16, gsrc[t] + k0 + 8);
            }
            CP_COMMIT();
            CP_WAIT1();
        } else {
            CP_WAIT0();
        }
        __syncthreads();

        const uint32_t sb = smb + (ch & 1) * STAGE_BYTES;
#pragma unroll
        for (int ks = 0; ks < 2; ks++) {
            uint32_t ahi[2][4], alo[2][4];
#pragma unroll
            for (int mi = 0; mi < 2; mi++) {
                const uint32_t o = aoff + (uint32_t)(mi * 16 * LDT) * 2 + ks * 32;
                ldmatrix_x4(ahi[mi], sb + o);
                ldmatrix_x4(alo[mi], sb + TILE_BYTES + o);
            }
#pragma unroll
            for (int g = 0; g < 4; g++) {
                uint32_t bhi[4], blo[4];
                const uint32_t o = boff + (uint32_t)(g * 16 * LDT) * 2 + ks * 32;
                ldmatrix_x4(bhi, sb + 2 * TILE_BYTES + o);
                ldmatrix_x4(blo, sb + 3 * TILE_BYTES + o);
                // term-major: dependent writes to same acc are 4 apart
                mma_bf16(acc[0][2 * g + 0], ahi[0], bhi[0], bhi[1]);
                mma_bf16(acc[0][2 * g + 1], ahi[0], bhi[2], bhi[3]);
                mma_bf16(acc[1][2 * g + 0], ahi[1], bhi[0], bhi[1]);
                mma_bf16(acc[1][2 * g + 1], ahi[1], bhi[2], bhi[3]);
                mma_bf16(acc[0][2 * g + 0], ahi[0], blo[0], blo[1]);
                mma_bf16(acc[0][2 * g + 1], ahi[0], blo[2], blo[3]);
                mma_bf16(acc[1][2 * g + 0], ahi[1], blo[0], blo[1]);
                mma_bf16(acc[1][2 * g + 1], ahi[1], blo[2], blo[3]);
                mma_bf16(acc[0][2 * g + 0], alo[0], bhi[0], bhi[1]);
                mma_bf16(acc[0][2 * g + 1], alo[0], bhi[2], bhi[3]);
                mma_bf16(acc[1][2 * g + 0], alo[1], bhi[0], bhi[1]);
                mma_bf16(acc[1][2 * g + 1], alo[1], bhi[2], bhi[3]);
            }
        }
        __syncthreads();
    }

    // ---- epilogue ----
#pragma unroll
    for (int mi = 0; mi < 2; mi++) {
        const int row = cRow + warp_row * 32 + mi * 16 + (lane >> 2);
#pragma unroll
        for (int ni = 0; ni < 8; ni++) {
            const int col = cCol + warp_col * 64 + ni * 8 + (lane & 3) * 2;
            if (SPLIT_OUT) {
                const size_t i0 = (size_t)row * ldc + col;
                const size_t i1 = (size_t)(row + 8) * ldc + col;
                split2_store(acc[mi][ni][0], acc[mi][ni][1], &Chi[i0], &Clo[i0]);
                split2_store(acc[mi][ni][2], acc[mi][ni][3], &Chi[i1], &Clo[i1]);
            } else {
                float2 v0 = make_float2(acc[mi][ni][0], acc[mi][ni][1]);
                float2 v1 = make_float2(acc[mi][ni][2], acc[mi][ni][3]);
                if (bias != nullptr) {
                    float2 bb = *(const float2*)&bias[col];
                    v0.x += bb.x; v0.y += bb.y;
                    v1.x += bb.x; v1.y += bb.y;
                }
                *(float2*)&C[(size_t)row * ldc + col]       = v0;
                *(float2*)&C[(size_t)(row + 8) * ldc + col] = v1;
            }
        }
    }
}

// ---------------------------------------------------------------------------
// HMMA causal flash-attention (MQA), bf16 hi/lo in, bf16 hi/lo out.
// Block = (128-row Q tile, h, b); 8 warps. Dynamic SMEM = 2 x 36,864 B
// stages, cp.async double-buffered KV (Khi/Klo/Vhi/Vlo, [64 x 72] each).
// Q is staged in stage 0 first, fragments extracted, then stage recycled.
// ---------------------------------------------------------------------------
#define LDA 72
#define ATT_STAGE 36864            // bytes per stage
#define ATT_DSMEM (2 * ATT_STAGE)  // 73728

__global__ __launch_bounds__(256, 1)
void attn_hmma(const __nv_bfloat16* __restrict__ QKVhi,
               const __nv_bfloat16* __restrict__ QKVlo,
               __nv_bfloat16* __restrict__ Zhi,
               __nv_bfloat16* __restrict__ Zlo) {
    extern __shared__ __nv_bfloat16 asm_[];
    const uint32_t smb = smem_to_u32(asm_);
    const int tid  = threadIdx.x;
    const int lane = tid & 31;
    const int w    = tid >> 5;
    const int qb = blockIdx.x, h = blockIdx.y, b = blockIdx.z;
    const int qbase = qb * 128;

    // ---- Phase A: copy pre-scaled Q hi/lo into stage 0 ----
    {
        const int row = tid >> 1, part = (tid & 1) * 32;
        const size_t gidx = ((size_t)(b * 2048 + qbase + row)) * 1152 + h * 64 + part;
        const uint4* qh = (const uint4*)(QKVhi + gidx);
        const uint4* ql = (const uint4*)(QKVlo + gidx);
        uint4* dh = (uint4*)(asm_ + row * LDA + part);
        uint4* dl = (uint4*)(asm_ + 9216 + row * LDA + part);
#pragma unroll
        for (int c = 0; c < 4; c++) { dh[c] = qh[c]; dl[c] = ql[c]; }
    }
    __syncthreads();

    uint32_t qhi[4][4], qlo[4][4];
    {
        const uint32_t aoff = ((uint32_t)(w * 16 + (lane & 15)) * LDA + ((lane >> 4) << 3)) * 2;
#pragma unroll
        for (int kc = 0; kc < 4; kc++) {
            ldmatrix_x4(qhi[kc], smb + aoff + kc * 32);
            ldmatrix_x4(qlo[kc], smb + 18432 + aoff + kc * 32);
        }
    }
    __syncthreads();  // stages now free for KV

    float acc_o[8][4];
#pragma unroll
    for (int i = 0; i < 8; i++)
#pragma unroll
        for (int j = 0; j < 4; j++) acc_o[i][j] = 0.0f;
    float m0 = -1e30f, m1 = -1e30f, l0 = 0.0f, l1 = 0.0f;

    const int r0    = lane >> 2;
    const int g0    = qbase + w * 16 + r0;
    const int colq  = (lane & 3) * 2;
    const int rmaxw = qbase + w * 16 + 15;

    const uint32_t koffb = ((uint32_t)((lane & 7) + ((lane >> 4) << 3)) * LDA +
                           (((lane >> 3) & 1) << 3)) * 2;
    const uint32_t mi4   = lane >> 3;
    const uint32_t voffb = ((uint32_t)((mi4 & 1) * 8 + (lane & 7)) * LDA +
                           ((mi4 >> 1) << 3)) * 2;

    // cp.async loader mapping: row = tid>>2 (0..63), seg = (tid&3)*16 bf16
    const int crow = tid >> 2, cseg = (tid & 3) * 16;
    const uint32_t cdst = (uint32_t)(crow * LDA + cseg) * 2;

    const int nkv = 2 * (qb + 1);

    // prologue: stream KV tile 0 into stage 0
    {
        const size_t kidx = ((size_t)(b * 2048 + crow)) * 1152 + 1024 + cseg;
        const uint32_t d = smb + cdst;
        CP_ASYNC16(d,         QKVhi + kidx);      CP_ASYNC16(d + 16,         QKVhi + kidx + 8);
        CP_ASYNC16(d +  9216, QKVlo + kidx);      CP_ASYNC16(d +  9216 + 16, QKVlo + kidx + 8);
        CP_ASYNC16(d + 18432, QKVhi + kidx + 64); CP_ASYNC16(d + 18432 + 16, QKVhi + kidx + 72);
        CP_ASYNC16(d + 27648, QKVlo + kidx + 64); CP_ASYNC16(d + 27648 + 16, QKVlo + kidx + 72);
    }
    CP_COMMIT();

    for (int kvt = 0; kvt < nkv; kvt++) {
        if (kvt + 1 < nkv) {
            const size_t kidx = ((size_t)(b * 2048 + (kvt + 1) * 64 + crow)) * 1152 + 1024 + cseg;
            const uint32_t d = smb + ((kvt + 1) & 1) * ATT_STAGE + cdst;
            CP_ASYNC16(d,         QKVhi + kidx);      CP_ASYNC16(d + 16,         QKVhi + kidx + 8);
            CP_ASYNC16(d +  9216, QKVlo + kidx);      CP_ASYNC16(d +  9216 + 16, QKVlo + kidx + 8);
            CP_ASYNC16(d + 18432, QKVhi + kidx + 64); CP_ASYNC16(d + 18432 + 16, QKVhi + kidx + 72);
            CP_ASYNC16(d + 27648, QKVlo + kidx + 64); CP_ASYNC16(d + 27648 + 16, QKVlo + kidx + 72);
            CP_COMMIT();
            CP_WAIT1();
        } else {
            CP_WAIT0();
        }
        __syncthreads();

        const uint32_t sb = smb + (kvt & 1) * ATT_STAGE;

        if (kvt * 64 <= rmaxw) {
            // ---- S = Q . K^T (bf16 x3, term-major interleave) ----
            float s[8][4];
#pragma unroll
            for (int i = 0; i < 8; i++)
#pragma unroll
                for (int j = 0; j < 4; j++) s[i][j] = 0.0f;
#pragma unroll
            for (int kc = 0; kc < 4; kc++) {
#pragma unroll
                for (int nbp = 0; nbp < 4; nbp++) {
                    uint32_t khi[4], klo[4];
                    const uint32_t off = koffb + (uint32_t)(nbp * 16 * LDA + kc * 16) * 2;
                    ldmatrix_x4(khi, sb + off);
                    ldmatrix_x4(klo, sb + 9216 + off);
                    mma_bf16(s[2 * nbp],     qhi[kc], khi[0], khi[1]);
                    mma_bf16(s[2 * nbp + 1], qhi[kc], khi[2], khi[3]);
                    mma_bf16(s[2 * nbp],     qhi[kc], klo[0], klo[1]);
                    mma_bf16(s[2 * nbp + 1], qhi[kc], klo[2], klo[3]);
                    mma_bf16(s[2 * nbp],     qlo[kc], khi[0], khi[1]);
                    mma_bf16(s[2 * nbp + 1], qlo[kc], khi[2], khi[3]);
                }
            }
            // ---- causal mask (diagonal tiles only) ----
            if (kvt >= 2 * qb) {
                const int jb = kvt * 64 + colq;
#pragma unroll
                for (int ni = 0; ni < 8; ni++) {
                    const int j0 = jb + ni * 8;
                    if (j0     > g0)     s[ni][0] = -1e30f;
                    if (j0 + 1 > g0)     s[ni][1] = -1e30f;
                    if (j0     > g0 + 8) s[ni][2] = -1e30f;
                    if (j0 + 1 > g0 + 8) s[ni][3] = -1e30f;
                }
            }
            // ---- online softmax ----
            float mt0 = -1e30f, mt1 = -1e30f;
#pragma unroll
            for (int ni = 0; ni < 8; ni++) {
                mt0 = fmaxf(mt0, fmaxf(s[ni][0], s[ni][1]));
                mt1 = fmaxf(mt1, fmaxf(s[ni][2], s[ni][3]));
            }
            mt0 = fmaxf(mt0, __shfl_xor_sync(0xffffffffu, mt0, 1));
            mt0 = fmaxf(mt0, __shfl_xor_sync(0xffffffffu, mt0, 2));
            mt1 = fmaxf(mt1, __shfl_xor_sync(0xffffffffu, mt1, 1));
            mt1 = fmaxf(mt1, __shfl_xor_sync(0xffffffffu, mt1, 2));
            const float m0n = fmaxf(fmaxf(m0, mt0), -1e20f);
            const float m1n = fmaxf(fmaxf(m1, mt1), -1e20f);
            const float a0 = __expf(m0 - m0n), a1 = __expf(m1 - m1n);
            l0 *= a0; l1 *= a1;
#pragma unroll
            for (int ni = 0; ni < 8; ni++) {
                acc_o[ni][0] *= a0; acc_o[ni][1] *= a0;
                acc_o[ni][2] *= a1; acc_o[ni][3] *= a1;
            }
            m0 = m0n; m1 = m1n;

            // P = exp(S - m): split hi/lo, build A fragments per k16 step
            uint32_t pahi[4][4], palo[4][4];
#pragma unroll
            for (int ni = 0; ni < 8; ni++) {
                const float p0 = __expf(s[ni][0] - m0n);
                const float p1 = __expf(s[ni][1] - m0n);
                const float p2 = __expf(s[ni][2] - m1n);
                const float p3 = __expf(s[ni][3] - m1n);
                l0 += p0 + p1; l1 += p2 + p3;
                const int kc = ni >> 1;
                const int o  = (ni & 1) * 2;
                const __nv_bfloat16 h0 = __float2bfloat16(p0);
                const __nv_bfloat16 h1 = __float2bfloat16(p1);
                const __nv_bfloat16 h2 = __float2bfloat16(p2);
                const __nv_bfloat16 h3 = __float2bfloat16(p3);
                pahi[kc][o]     = pack2(h0, h1);
                pahi[kc][o + 1] = pack2(h2, h3);
                palo[kc][o]     = pack_bf16f(p0 - __bfloat162float(h0),
                                             p1 - __bfloat162float(h1));
                palo[kc][o + 1] = pack_bf16f(p2 - __bfloat162float(h2),
                                             p3 - __bfloat162float(h3));
            }

            // ---- O += P . V (bf16 x3, term-major interleave) ----
#pragma unroll
            for (int kc = 0; kc < 4; kc++) {
#pragma unroll
                for (int nb = 0; nb < 4; nb++) {
                    uint32_t vhi[4], vlo[4];
                    const uint32_t off = voffb + (uint32_t)(kc * 16 * LDA + nb * 16) * 2;
                    ldmatrix_x4_trans(vhi, sb + 18432 + off);
                    ldmatrix_x4_trans(vlo, sb + 27648 + off);
                    mma_bf16(acc_o[2 * nb],     pahi[kc], vhi[0], vhi[1]);
                    mma_bf16(acc_o[2 * nb + 1], pahi[kc], vhi[2], vhi[3]);
                    mma_bf16(acc_o[2 * nb],     pahi[kc], vlo[0], vlo[1]);
                    mma_bf16(acc_o[2 * nb + 1], pahi[kc], vlo[2], vlo[3]);
                    mma_bf16(acc_o[2 * nb],     palo[kc], vhi[0], vhi[1]);
                    mma_bf16(acc_o[2 * nb + 1], palo[kc], vhi[2], vhi[3]);
                }
            }
        }
        __syncthreads();
    }

    // ---- finalize ----
    l0 += __shfl_xor_sync(0xffffffffu, l0, 1);
    l0 += __shfl_xor_sync(0xffffffffu, l0, 2);
    l1 += __shfl_xor_sync(0xffffffffu, l1, 1);
    l1 += __shfl_xor_sync(0xffffffffu, l1, 2);
    const float inv0 = 1.0f / l0, inv1 = 1.0f / l1;
    const size_t z0i = ((size_t)(b * 2048 + g0)) * 1024 + h * 64 + colq;
    const size_t z1i = z0i + (size_t)8 * 1024;
#pragma unroll
    for (int ni = 0; ni < 8; ni++) {
        split2_store(acc_o[ni][0] * inv0, acc_o[ni][1] * inv0,
                     &Zhi[z0i + ni * 8], &Zlo[z0i + ni * 8]);
        split2_store(acc_o[ni][2] * inv1, acc_o[ni][3] * inv1,
                     &Zhi[z1i + ni * 8], &Zlo[z1i + ni * 8]);
    }
}

// ---------------------------------------------------------------------------
// Launch
// ---------------------------------------------------------------------------
extern "C" void kernel_launch(void* const* d_in, const int* in_sizes, int n_in,
                              void* d_out, int out_size) {
    const float* x  = (const float*)d_in[0];  // (2,2048,1024)
    const float* Wq = (const float*)d_in[1];  // (1024,1024)
    const float* Wk = (const float*)d_in[2];  // (1024,64)
    const float* Wv = (const float*)d_in[3];  // (1024,64)
    const float* Wo = (const float*)d_in[4];  // (1024,1024)
    const float* bo = (const float*)d_in[5];  // (1024,)

    __nv_bfloat16 *QKVhi, *QKVlo, *Xhi, *Xlo, *Wthi, *Wtlo, *Wothi, *Wotlo, *Zhi, *Zlo;
    cudaGetSymbolAddress((void**)&QKVhi, g_QKVhi);
    cudaGetSymbolAddress((void**)&QKVlo, g_QKVlo);
    cudaGetSymbolAddress((void**)&Xhi,   g_Xhi);
    cudaGetSymbolAddress((void**)&Xlo,   g_Xlo);
    cudaGetSymbolAddress((void**)&Wthi,  g_Wthi);
    cudaGetSymbolAddress((void**)&Wtlo,  g_Wtlo);
    cudaGetSymbolAddress((void**)&Wothi, g_Wothi);
    cudaGetSymbolAddress((void**)&Wotlo, g_Wotlo);
    cudaGetSymbolAddress((void**)&Zhi,   g_Zhi);
    cudaGetSymbolAddress((void**)&Zlo,   g_Zlo);

    cudaFuncSetAttribute(hmma_gemm<true>,
                         cudaFuncAttributeMaxDynamicSharedMemorySize, GEMM_DSMEM);
    cudaFuncSetAttribute(hmma_gemm<false>,
                         cudaFuncAttributeMaxDynamicSharedMemorySize, GEMM_DSMEM);
    cudaFuncSetAttribute(attn_hmma,
                         cudaFuncAttributeMaxDynamicSharedMemorySize, ATT_DSMEM);

    // 1) precision-split input / build weights (Wq pre-scaled by 1/8)
    split_f32_bf16<<<CDIV(4096 * 1024 / 4, 256), 256>>>(x, Xhi, Xlo, 4096 * 1024 / 4);
    build_wall_t<<<CDIV(1152 * 1024, 256), 256>>>(Wq, Wk, Wv, Wthi, Wtlo);
    build_wo_t<<<CDIV(1024 * 1024, 256), 256>>>(Wo, Wothi, Wotlo);

    // 2) QKV = X @ [Wq/8|Wk|Wv] -> split bf16 hi/lo directly
    hmma_gemm<true><<<dim3(1152 / 128, 4096 / 128), 256, GEMM_DSMEM>>>(
        Xhi, Xlo, Wthi, Wtlo, nullptr, nullptr, QKVhi, QKVlo, 1024, 1152);

    // 3) causal flash-attention MQA on HMMA (double-buffered KV)
    attn_hmma<<<dim3(16, 16, 2), 256, ATT_DSMEM>>>(QKVhi, QKVlo, Zhi, Zlo);

    // 4) out = Z @ Wo + bo -> d_out (fp32)
    hmma_gemm<false><<<dim3(1024 / 128, 4096 / 128), 256, GEMM_DSMEM>>>(
        Zhi, Zlo, Wothi, Wotlo, (float*)d_out, bo, nullptr, nullptr, 1024, 1024);
}